// round 9
// baseline (speedup 1.0000x reference)
#include <cuda_runtime.h>

#define NN    384
#define TS    32
#define KC    16
#define NT    (NN / TS)      // 12
#define NBLK  (NT * NT)      // 144 < 148 SMs -> co-resident grid barrier safe
#define NG    8              // K-split groups of 64 threads
#define PP    36             // smem row pitch (floats), 144B -> float4 aligned
#define BOFF  (NG * KC * PP) // Bsm offset in pool

typedef unsigned long long ull;

// Scratch (device globals: no allocation allowed)
__device__ __align__(16) float g_u[NN * NN];
__device__ __align__(16) float g_W[NN * NN];

// Distributed grid barrier: per-block flags + one release word (monotone epochs)
__device__ unsigned g_flags[NBLK];
__device__ unsigned g_gen;

__device__ __forceinline__ void grid_barrier(unsigned epoch) {
    __syncthreads();
    if (blockIdx.x == 0) {
        int t = threadIdx.x;
        if (t >= 1 && t < NBLK) {
            while (*(volatile unsigned*)&g_flags[t] < epoch) { }
        }
        __syncthreads();
        if (t == 0) {
            __threadfence();
            *(volatile unsigned*)&g_gen = epoch;
        }
    } else {
        if (threadIdx.x == 0) {
            __threadfence();
            *(volatile unsigned*)&g_flags[blockIdx.x] = epoch;
            while (*(volatile unsigned*)&g_gen < epoch) { }
        }
    }
    __syncthreads();
    __threadfence();
}

__device__ __forceinline__ void group_barrier(int g) {
    asm volatile("bar.sync %0, 64;" :: "r"(1 + g) : "memory");
}

__device__ __forceinline__ float decode_lam(const void* p) {
    int raw = *(const int*)p;
    unsigned ub = (unsigned)raw;
    if (ub < 0x01000000u) return (float)raw;   // small-int bits (int32/int64 low)
    return __int_as_float(raw);                // float32 bits
}

// Packed fp32x2 helpers (FFMA2 — not emitted by ptxas from C++)
__device__ __forceinline__ void ffma2(ull& d, ull a, ull b) {
    asm("fma.rn.f32x2 %0, %1, %2, %0;" : "+l"(d) : "l"(a), "l"(b));
}
__device__ __forceinline__ ull dup2(float x) {
    ull r; asm("mov.b64 %0, {%1, %1};" : "=l"(r) : "f"(x)); return r;
}
__device__ __forceinline__ float2 upk(ull v) {
    float2 f; asm("mov.b64 {%0, %1}, %2;" : "=f"(f.x), "=f"(f.y) : "l"(v)); return f;
}

#define ASM(gg, k, r) smem_pool[((gg) * KC + (k)) * PP + (r)]
#define BSM(gg, k, c) smem_pool[BOFF + ((gg) * KC + (k)) * PP + (c)]

// P1: u = (adj>0 && i!=j) ? exp(-lam*dist) : 0
// P2: W = od/S on S = u + offdiag(u@u)
// P3: out = u .* (W + [W | u^T] @ [u^T ; W])    (single K=768 GEMM)
// 8 K-groups x 64 threads; 4x4 micro-tile; packed f32x2 accumulation.
__global__ __launch_bounds__(512, 1)
void fused_kernel(const float* __restrict__ od,
                  const int*   __restrict__ adj,
                  const float* __restrict__ dist,
                  const void*  __restrict__ lam_p,
                  float*       __restrict__ out) {
    __shared__ __align__(16) float smem_pool[2 * NG * KC * PP];  // 36864 B

    const int tid  = threadIdx.x;
    const int g    = tid >> 6;            // group 0..7
    const int gtid = tid & 63;
    const int tyy = gtid >> 3;            // rows 4*tyy..+3
    const int txx = gtid & 7;             // cols 4*txx..+3
    const int lrT = gtid >> 1;            // transposed-load row 0..31
    const int lhT = gtid & 1;             // transposed-load k-half
    const int krN = gtid >> 2;            // natural-load k-row 0..15
    const int cqN = gtid & 3;             // natural-load col quads cq, cq+4
    const int tileX = blockIdx.x % NT;
    const int tileY = blockIdx.x / NT;
    const int rowBlk = tileY * TS;
    const int colBlk = tileX * TS;
    float* red = smem_pool;               // 32KB reduction scratch (reused)

    const unsigned base = *(volatile unsigned*)&g_gen;

    const int er  = tid >> 4;             // epilogue row 0..31
    const int ec0 = 2 * (tid & 15);       // epilogue col pair

    // ---------------- Phase 1: build u (2 elems/thread) ---------------------
    {
        const float lam = decode_lam(lam_p);
        int bidx = blockIdx.x * 1024 + tid * 2;
        int2   a2 = *(const int2*)&adj[bidx];
        float2 d2 = *(const float2*)&dist[bidx];
        int r = bidx / NN;
        int c = bidx - r * NN;
        float2 v;
        v.x = (a2.x > 0 && r != c    ) ? expf(-lam * d2.x) : 0.f;
        v.y = (a2.y > 0 && r != c + 1) ? expf(-lam * d2.y) : 0.f;
        *(float2*)&g_u[bidx] = v;
    }
    grid_barrier(base + 1);

    // ---------------- Phase 2: G = u@u, W epilogue --------------------------
    {
        ull acc[2][4];
#pragma unroll
        for (int i = 0; i < 2; ++i)
#pragma unroll
            for (int j = 0; j < 4; ++j) acc[i][j] = 0ull;

        int p0 = g * 3 * KC;
        float4 pa0 = *(const float4*)&g_u[(rowBlk + lrT) * NN + p0 + 8 * lhT];
        float4 pa1 = *(const float4*)&g_u[(rowBlk + lrT) * NN + p0 + 8 * lhT + 4];
        float4 pb0 = *(const float4*)&g_u[(p0 + krN) * NN + colBlk + 4 * cqN];
        float4 pb1 = *(const float4*)&g_u[(p0 + krN) * NN + colBlk + 4 * cqN + 16];
#pragma unroll 1
        for (int t = 0; t < 3; ++t) {
            group_barrier(g);                       // prev compute done
            ASM(g, 8 * lhT + 0, lrT) = pa0.x;       // A^T store
            ASM(g, 8 * lhT + 1, lrT) = pa0.y;
            ASM(g, 8 * lhT + 2, lrT) = pa0.z;
            ASM(g, 8 * lhT + 3, lrT) = pa0.w;
            ASM(g, 8 * lhT + 4, lrT) = pa1.x;
            ASM(g, 8 * lhT + 5, lrT) = pa1.y;
            ASM(g, 8 * lhT + 6, lrT) = pa1.z;
            ASM(g, 8 * lhT + 7, lrT) = pa1.w;
            *(float4*)&BSM(g, krN, 4 * cqN)      = pb0;   // natural store
            *(float4*)&BSM(g, krN, 4 * cqN + 16) = pb1;
            group_barrier(g);                       // stores visible
            if (t + 1 < 3) {
                int pn = (g * 3 + t + 1) * KC;
                pa0 = *(const float4*)&g_u[(rowBlk + lrT) * NN + pn + 8 * lhT];
                pa1 = *(const float4*)&g_u[(rowBlk + lrT) * NN + pn + 8 * lhT + 4];
                pb0 = *(const float4*)&g_u[(pn + krN) * NN + colBlk + 4 * cqN];
                pb1 = *(const float4*)&g_u[(pn + krN) * NN + colBlk + 4 * cqN + 16];
            }
#pragma unroll
            for (int k = 0; k < KC; ++k) {
                ull a01 = *(const ull*)&ASM(g, k, 4 * tyy);
                ull a23 = *(const ull*)&ASM(g, k, 4 * tyy + 2);
                float4 b = *(const float4*)&BSM(g, k, 4 * txx);
                ull b0 = dup2(b.x), b1 = dup2(b.y), b2 = dup2(b.z), b3 = dup2(b.w);
                ffma2(acc[0][0], a01, b0); ffma2(acc[1][0], a23, b0);
                ffma2(acc[0][1], a01, b1); ffma2(acc[1][1], a23, b1);
                ffma2(acc[0][2], a01, b2); ffma2(acc[1][2], a23, b2);
                ffma2(acc[0][3], a01, b3); ffma2(acc[1][3], a23, b3);
            }
        }
        __syncthreads();
        {
            float s[4][4];
#pragma unroll
            for (int c = 0; c < 4; ++c) {
                float2 p = upk(acc[0][c]); s[0][c] = p.x; s[1][c] = p.y;
                float2 q = upk(acc[1][c]); s[2][c] = q.x; s[3][c] = q.y;
            }
#pragma unroll
            for (int r = 0; r < 4; ++r)
                *(float4*)&red[g * 1024 + (4 * tyy + r) * 32 + 4 * txx] =
                    make_float4(s[r][0], s[r][1], s[r][2], s[r][3]);
        }
        __syncthreads();
        {
            float s0 = 0.f, s1 = 0.f;
#pragma unroll
            for (int gg = 0; gg < NG; ++gg) {
                float2 v = *(const float2*)&red[gg * 1024 + er * 32 + ec0];
                s0 += v.x; s1 += v.y;
            }
            int r = rowBlk + er;
            int c0 = colBlk + ec0;
            int idx = r * NN + c0;
            float2 uv  = *(const float2*)&g_u[idx];
            float2 odv = *(const float2*)&od[idx];
            float S0 = uv.x + ((r != c0)     ? s0 : 0.f);
            float S1 = uv.y + ((r != c0 + 1) ? s1 : 0.f);
            float2 w2;
            w2.x = (odv.x > 0.f && r != c0     && S0 > 0.f) ? (odv.x / S0) : 0.f;
            w2.y = (odv.y > 0.f && r != c0 + 1 && S1 > 0.f) ? (odv.y / S1) : 0.f;
            *(float2*)&g_W[idx] = w2;
        }
    }
    grid_barrier(base + 2);

    // ---------------- Phase 3: C = [W | u^T] @ [u^T ; W] --------------------
    // Groups 0-3: k in [0,384): A=W rows (transposed), B=u rows@colBlk (transposed)
    // Groups 4-7: k in [384,768): A=u k-rows@rowBlk (natural), B=W k-rows (natural)
    {
        ull acc[2][4];
#pragma unroll
        for (int i = 0; i < 2; ++i)
#pragma unroll
            for (int j = 0; j < 4; ++j) acc[i][j] = 0ull;

        const bool first = (g < 4);
        float4 pa0, pa1, pb0, pb1;
        if (first) {
            int p0 = g * 6 * KC;
            pa0 = *(const float4*)&g_W[(rowBlk + lrT) * NN + p0 + 8 * lhT];
            pa1 = *(const float4*)&g_W[(rowBlk + lrT) * NN + p0 + 8 * lhT + 4];
            pb0 = *(const float4*)&g_u[(colBlk + lrT) * NN + p0 + 8 * lhT];
            pb1 = *(const float4*)&g_u[(colBlk + lrT) * NN + p0 + 8 * lhT + 4];
        } else {
            int p0 = (g - 4) * 6 * KC;
            pa0 = *(const float4*)&g_u[(p0 + krN) * NN + rowBlk + 4 * cqN];
            pa1 = *(const float4*)&g_u[(p0 + krN) * NN + rowBlk + 4 * cqN + 16];
            pb0 = *(const float4*)&g_W[(p0 + krN) * NN + colBlk + 4 * cqN];
            pb1 = *(const float4*)&g_W[(p0 + krN) * NN + colBlk + 4 * cqN + 16];
        }
#pragma unroll 1
        for (int t = 0; t < 6; ++t) {
            group_barrier(g);
            if (first) {                             // both transposed stores
                ASM(g, 8 * lhT + 0, lrT) = pa0.x;
                ASM(g, 8 * lhT + 1, lrT) = pa0.y;
                ASM(g, 8 * lhT + 2, lrT) = pa0.z;
                ASM(g, 8 * lhT + 3, lrT) = pa0.w;
                ASM(g, 8 * lhT + 4, lrT) = pa1.x;
                ASM(g, 8 * lhT + 5, lrT) = pa1.y;
                ASM(g, 8 * lhT + 6, lrT) = pa1.z;
                ASM(g, 8 * lhT + 7, lrT) = pa1.w;
                BSM(g, 8 * lhT + 0, lrT) = pb0.x;
                BSM(g, 8 * lhT + 1, lrT) = pb0.y;
                BSM(g, 8 * lhT + 2, lrT) = pb0.z;
                BSM(g, 8 * lhT + 3, lrT) = pb0.w;
                BSM(g, 8 * lhT + 4, lrT) = pb1.x;
                BSM(g, 8 * lhT + 5, lrT) = pb1.y;
                BSM(g, 8 * lhT + 6, lrT) = pb1.z;
                BSM(g, 8 * lhT + 7, lrT) = pb1.w;
            } else {                                 // both natural stores
                *(float4*)&ASM(g, krN, 4 * cqN)      = pa0;
                *(float4*)&ASM(g, krN, 4 * cqN + 16) = pa1;
                *(float4*)&BSM(g, krN, 4 * cqN)      = pb0;
                *(float4*)&BSM(g, krN, 4 * cqN + 16) = pb1;
            }
            group_barrier(g);
            if (t + 1 < 6) {
                if (first) {
                    int p0 = (g * 6 + t + 1) * KC;
                    pa0 = *(const float4*)&g_W[(rowBlk + lrT) * NN + p0 + 8 * lhT];
                    pa1 = *(const float4*)&g_W[(rowBlk + lrT) * NN + p0 + 8 * lhT + 4];
                    pb0 = *(const float4*)&g_u[(colBlk + lrT) * NN + p0 + 8 * lhT];
                    pb1 = *(const float4*)&g_u[(colBlk + lrT) * NN + p0 + 8 * lhT + 4];
                } else {
                    int p0 = ((g - 4) * 6 + t + 1) * KC;
                    pa0 = *(const float4*)&g_u[(p0 + krN) * NN + rowBlk + 4 * cqN];
                    pa1 = *(const float4*)&g_u[(p0 + krN) * NN + rowBlk + 4 * cqN + 16];
                    pb0 = *(const float4*)&g_W[(p0 + krN) * NN + colBlk + 4 * cqN];
                    pb1 = *(const float4*)&g_W[(p0 + krN) * NN + colBlk + 4 * cqN + 16];
                }
            }
#pragma unroll
            for (int k = 0; k < KC; ++k) {
                ull a01 = *(const ull*)&ASM(g, k, 4 * tyy);
                ull a23 = *(const ull*)&ASM(g, k, 4 * tyy + 2);
                float4 b = *(const float4*)&BSM(g, k, 4 * txx);
                ull b0 = dup2(b.x), b1 = dup2(b.y), b2 = dup2(b.z), b3 = dup2(b.w);
                ffma2(acc[0][0], a01, b0); ffma2(acc[1][0], a23, b0);
                ffma2(acc[0][1], a01, b1); ffma2(acc[1][1], a23, b1);
                ffma2(acc[0][2], a01, b2); ffma2(acc[1][2], a23, b2);
                ffma2(acc[0][3], a01, b3); ffma2(acc[1][3], a23, b3);
            }
        }
        __syncthreads();
        {
            float s[4][4];
#pragma unroll
            for (int c = 0; c < 4; ++c) {
                float2 p = upk(acc[0][c]); s[0][c] = p.x; s[1][c] = p.y;
                float2 q = upk(acc[1][c]); s[2][c] = q.x; s[3][c] = q.y;
            }
#pragma unroll
            for (int r = 0; r < 4; ++r)
                *(float4*)&red[g * 1024 + (4 * tyy + r) * 32 + 4 * txx] =
                    make_float4(s[r][0], s[r][1], s[r][2], s[r][3]);
        }
        __syncthreads();
        {
            float s0 = 0.f, s1 = 0.f;
#pragma unroll
            for (int gg = 0; gg < NG; ++gg) {
                float2 v = *(const float2*)&red[gg * 1024 + er * 32 + ec0];
                s0 += v.x; s1 += v.y;
            }
            int r = rowBlk + er;
            int c0 = colBlk + ec0;
            int idx = r * NN + c0;
            float2 uv = *(const float2*)&g_u[idx];
            float2 wv = *(const float2*)&g_W[idx];
            float2 o;
            o.x = uv.x * (wv.x + s0);
            o.y = uv.y * (wv.y + s1);
            *(float2*)&out[idx] = o;
        }
    }
}

extern "C" void kernel_launch(void* const* d_in, const int* in_sizes, int n_in,
                              void* d_out, int out_size) {
    const float* od   = (const float*)d_in[0];
    const int*   adj  = (const int*)d_in[1];
    const float* dist = (const float*)d_in[2];
    const void*  lamp = d_in[3];
    float* out = (float*)d_out;

    fused_kernel<<<NBLK, 512>>>(od, adj, dist, lamp, out);
}